// round 1
// baseline (speedup 1.0000x reference)
#include <cuda_runtime.h>

#define HH 4096
#define WW 4096
#define TX 128
#define TY 32
#define NTHREADS 256

// Global accumulators (scratch via __device__ globals — no allocation)
__device__ double g_sum_d2;
__device__ double g_sum_G;
__device__ unsigned long long g_count;

__device__ __forceinline__ int refl(int i, int n) {
    // reflect-101: -1 -> 1, n -> n-2
    if (i < 0) i = -i;
    if (i >= n) i = 2 * n - 2 - i;
    return i;
}

__global__ void init_kernel() {
    g_sum_d2 = 0.0;
    g_sum_G  = 0.0;
    g_count  = 0ull;
}

__global__ __launch_bounds__(NTHREADS)
void loss_kernel(const float* __restrict__ pred, const float* __restrict__ target) {
    // d tile with 2-halo; also reused as the blurred tile (smaller) later
    __shared__ float sd[(TY + 4) * (TX + 4)];
    // horizontal-blur intermediate: rows keep 2-halo, cols 1-halo
    __shared__ float sh[(TY + 4) * (TX + 2)];
    __shared__ float r_d2[NTHREADS / 32];
    __shared__ float r_g [NTHREADS / 32];
    __shared__ int   r_c [NTHREADS / 32];

    const int gx0 = blockIdx.x * TX;
    const int gy0 = blockIdx.y * TY;
    const int tid = threadIdx.x;

    const int LW = TX + 4;          // loaded tile width
    const int BW = TX + 2;          // blurred tile width (1-halo)

    float loc_d2 = 0.f;
    float loc_g  = 0.f;
    int   loc_cnt = 0;

    // ---- Load d = pred - target over (TY+4) x (TX+4) with reflect-101 halo.
    //      Accumulate masked MSE terms only on core (unreflected) pixels.
    for (int idx = tid; idx < (TY + 4) * LW; idx += NTHREADS) {
        int r = idx / LW, c = idx % LW;
        int gy = gy0 + r - 2;
        int gx = gx0 + c - 2;
        int ry = refl(gy, HH);
        int rx = refl(gx, WW);
        float p = pred[ry * WW + rx];
        float t = target[ry * WW + rx];
        float d = p - t;
        sd[idx] = d;
        if (r >= 2 && r < TY + 2 && c >= 2 && c < TX + 2) {
            // core pixel: gy,gx inside image, visited exactly once over the grid
            if (t > 0.f) { loc_cnt += 1; loc_d2 += d * d; }
        }
    }
    __syncthreads();

    // ---- Horizontal blur [1,2,1]/4: rows [-2..TY+1], cols [-1..TX]
    for (int idx = tid; idx < (TY + 4) * BW; idx += NTHREADS) {
        int r = idx / BW, c = idx % BW;      // c: 0..TX+1 maps to sd col c+1
        int s = r * LW + (c + 1);
        sh[idx] = 0.25f * (sd[s - 1] + 2.f * sd[s] + sd[s + 1]);
    }
    __syncthreads();

    // ---- Vertical blur [1,2,1]/4 into sb (reuses sd): rows [-1..TY], cols [-1..TX]
    float* sb = sd;
    for (int idx = tid; idx < (TY + 2) * BW; idx += NTHREADS) {
        int r = idx / BW, c = idx % BW;      // sb row r maps to sh rows r..r+2
        sb[idx] = 0.25f * (sh[r * BW + c] + 2.f * sh[(r + 1) * BW + c] + sh[(r + 2) * BW + c]);
    }
    __syncthreads();

    // ---- Sobel on blurred tile; halo values already equal the reflect-101
    //      padded blurred image (symmetric filter + reflect commute).
    for (int idx = tid; idx < TY * TX; idx += NTHREADS) {
        int r = idx / TX, c = idx % TX;
        int b = (r + 1) * BW + (c + 1);
        float tl = sb[b - BW - 1], tc = sb[b - BW], tr = sb[b - BW + 1];
        float ml = sb[b - 1],                       mr = sb[b + 1];
        float bl = sb[b + BW - 1], bc = sb[b + BW], br = sb[b + BW + 1];
        float dx = (tr + 2.f * mr + br) - (tl + 2.f * ml + bl);
        float dy = (bl + 2.f * bc + br) - (tl + 2.f * tc + tr);
        loc_g += dx * dx - dy * dy;
    }

    // ---- Block reduction
    #pragma unroll
    for (int off = 16; off > 0; off >>= 1) {
        loc_d2  += __shfl_down_sync(0xffffffffu, loc_d2, off);
        loc_g   += __shfl_down_sync(0xffffffffu, loc_g,  off);
        loc_cnt += __shfl_down_sync(0xffffffffu, loc_cnt, off);
    }
    int wid = tid >> 5, lane = tid & 31;
    if (lane == 0) { r_d2[wid] = loc_d2; r_g[wid] = loc_g; r_c[wid] = loc_cnt; }
    __syncthreads();
    if (tid == 0) {
        float s2 = 0.f, sg = 0.f; int sc = 0;
        #pragma unroll
        for (int i = 0; i < NTHREADS / 32; i++) { s2 += r_d2[i]; sg += r_g[i]; sc += r_c[i]; }
        atomicAdd(&g_sum_d2, (double)s2);
        atomicAdd(&g_sum_G,  (double)sg);
        atomicAdd(&g_count,  (unsigned long long)sc);
    }
}

__global__ void finalize_kernel(float* __restrict__ out) {
    double n = (double)g_count;
    if (n < 1.0) n = 1.0;
    double mae = g_sum_d2 / n;
    double G   = g_sum_G / ((double)HH * (double)WW);
    out[0] = (float)(0.2 * G + 0.8 * mae);
}

extern "C" void kernel_launch(void* const* d_in, const int* in_sizes, int n_in,
                              void* d_out, int out_size) {
    const float* pred   = (const float*)d_in[0];
    const float* target = (const float*)d_in[1];
    float* out = (float*)d_out;

    init_kernel<<<1, 1>>>();
    dim3 grid(WW / TX, HH / TY);
    loss_kernel<<<grid, NTHREADS>>>(pred, target);
    finalize_kernel<<<1, 1>>>(out);
}

// round 2
// speedup vs baseline: 1.6602x; 1.6602x over previous
#include <cuda_runtime.h>

#define WW 4096
#define HH 4096
#define TY 128          // output rows per block
#define OUTC 28         // output columns per warp (32 loaded, 2-halo each side)
#define WARPS 8
#define NTHREADS 256

// Accumulators: zeroed at module load; finalize_kernel resets them after each
// read so every graph replay starts from a clean state (stateless per cycle).
__device__ double g_sum_d2 = 0.0;
__device__ double g_sum_G  = 0.0;
__device__ unsigned long long g_count = 0ull;

// Horizontal combined taps on d (blur*sobel, unscaled by 1/16):
//   A = smooth5 = [1,4,6,4,1],  B = deriv5 = [-1,-2,0,2,1]
__device__ __forceinline__ void hpass(float d, float& A, float& B) {
    float dm1 = __shfl_up_sync(0xffffffffu,   d, 1);
    float dm2 = __shfl_up_sync(0xffffffffu,   d, 2);
    float dp1 = __shfl_down_sync(0xffffffffu, d, 1);
    float dp2 = __shfl_down_sync(0xffffffffu, d, 2);
    A = (dm2 + dp2) + 4.0f * (dm1 + dp1) + 6.0f * d;
    B = (dp2 - dm2) + 2.0f * (dp1 - dm1);
}

__global__ __launch_bounds__(NTHREADS)
void loss_kernel(const float* __restrict__ pred, const float* __restrict__ target) {
    __shared__ float s_d2[WARPS], s_g[WARPS];
    __shared__ int   s_c[WARPS];

    const int lane = threadIdx.x & 31;
    const int wid  = threadIdx.x >> 5;
    const int s    = blockIdx.x * WARPS + wid;   // column strip index
    const int y0   = blockIdx.y * TY;

    // This lane's column (= its output column). Reflect-101 for halo/overshoot.
    const int x = s * OUTC - 2 + lane;
    int xr = (x < 0) ? -x : x;
    if (xr >= WW) xr = 2 * WW - 2 - xr;
    const bool is_out = (lane >= 2) && (lane < 30) && (x < WW);
    const float gsel  = is_out ? 1.0f : 0.0f;

    float accD2 = 0.0f, accG = 0.0f;
    int   cnt = 0;
    float A0, A1, A2, A3, B0, B1, B2, B3;

    // ---- Prologue: rows y0-2 .. y0+1 (fill vertical ring; MSE on last two) ----
    {
        int r, rr; float p, t, d, Av, Bv;

        r = y0 - 2; rr = (r < 0) ? -r : r;
        p = __ldg(pred + rr * WW + xr); t = __ldg(target + rr * WW + xr);
        d = p - t; hpass(d, A0, B0);

        r = y0 - 1; rr = (r < 0) ? -r : r;
        p = __ldg(pred + rr * WW + xr); t = __ldg(target + rr * WW + xr);
        d = p - t; hpass(d, A1, B1);

        r = y0;
        p = __ldg(pred + r * WW + xr); t = __ldg(target + r * WW + xr);
        d = p - t;
        if (is_out && t > 0.0f) { accD2 = fmaf(d, d, accD2); cnt++; }
        hpass(d, A2, B2);

        r = y0 + 1;
        p = __ldg(pred + r * WW + xr); t = __ldg(target + r * WW + xr);
        d = p - t;
        if (is_out && t > 0.0f) { accD2 = fmaf(d, d, accD2); cnt++; }
        hpass(d, A3, B3);
        (void)Av; (void)Bv;
    }

    // ---- Main stream: rows y0+2 .. y0+TY-1 (always interior, pointer walk) ----
    const float* pp = pred   + (y0 + 2) * WW + xr;
    const float* tp = target + (y0 + 2) * WW + xr;
    #pragma unroll 4
    for (int i = 0; i < TY - 2; i++) {
        float p = __ldg(pp);
        float t = __ldg(tp);
        pp += WW; tp += WW;
        float d = p - t;
        if (is_out && t > 0.0f) { accD2 = fmaf(d, d, accD2); cnt++; }
        float A4, B4; hpass(d, A4, B4);
        // output row y = r-2: dx = vsmooth(B), dy = vderiv(A)
        float dx = (B0 + B4) + 4.0f * (B1 + B3) + 6.0f * B2;
        float dy = (A4 - A0) + 2.0f * (A3 - A1);
        accG = fmaf(gsel, fmaf(dx, dx, -(dy * dy)), accG);
        A0 = A1; A1 = A2; A2 = A3; A3 = A4;
        B0 = B1; B1 = B2; B2 = B3; B3 = B4;
    }

    // ---- Epilogue: rows y0+TY, y0+TY+1 (bottom reflect; no MSE) ----
    #pragma unroll
    for (int k = 0; k < 2; k++) {
        int r = y0 + TY + k;
        int rr = (r >= HH) ? (2 * HH - 2 - r) : r;
        float p = __ldg(pred + rr * WW + xr);
        float t = __ldg(target + rr * WW + xr);
        float d = p - t;
        float A4, B4; hpass(d, A4, B4);
        float dx = (B0 + B4) + 4.0f * (B1 + B3) + 6.0f * B2;
        float dy = (A4 - A0) + 2.0f * (A3 - A1);
        accG = fmaf(gsel, fmaf(dx, dx, -(dy * dy)), accG);
        A0 = A1; A1 = A2; A2 = A3; A3 = A4;
        B0 = B1; B1 = B2; B2 = B3; B3 = B4;
    }

    // ---- Reduction: warp shuffle -> smem -> one thread -> 3 atomics ----
    #pragma unroll
    for (int off = 16; off > 0; off >>= 1) {
        accD2 += __shfl_down_sync(0xffffffffu, accD2, off);
        accG  += __shfl_down_sync(0xffffffffu, accG,  off);
        cnt   += __shfl_down_sync(0xffffffffu, cnt,   off);
    }
    if (lane == 0) { s_d2[wid] = accD2; s_g[wid] = accG; s_c[wid] = cnt; }
    __syncthreads();
    if (threadIdx.x == 0) {
        float t2 = 0.0f, tg = 0.0f; int tc = 0;
        #pragma unroll
        for (int i = 0; i < WARPS; i++) { t2 += s_d2[i]; tg += s_g[i]; tc += s_c[i]; }
        atomicAdd(&g_sum_d2, (double)t2);
        atomicAdd(&g_sum_G,  (double)tg);
        atomicAdd(&g_count,  (unsigned long long)tc);
    }
}

__global__ void finalize_kernel(float* __restrict__ out) {
    double n = (double)g_count;
    if (n < 1.0) n = 1.0;
    double mae = g_sum_d2 / n;
    // kernel taps were 16x the true dx/dy -> scale sum by 1/256
    double G = g_sum_G / (256.0 * (double)WW * (double)HH);
    out[0] = (float)(0.2 * G + 0.8 * mae);
    // reset for the next replay (keeps every launch sequence identical)
    g_sum_d2 = 0.0;
    g_sum_G  = 0.0;
    g_count  = 0ull;
}

extern "C" void kernel_launch(void* const* d_in, const int* in_sizes, int n_in,
                              void* d_out, int out_size) {
    const float* pred   = (const float*)d_in[0];
    const float* target = (const float*)d_in[1];
    float* out = (float*)d_out;

    const int nstrips = (WW + OUTC - 1) / OUTC;          // 147
    dim3 grid((nstrips + WARPS - 1) / WARPS, HH / TY);   // (19, 32)
    loss_kernel<<<grid, NTHREADS>>>(pred, target);
    finalize_kernel<<<1, 1>>>(out);
}